// round 1
// baseline (speedup 1.0000x reference)
#include <cuda_runtime.h>

// Problem constants (B=1, H=32, Q=1024, S=4096, D=128)
#define SEQ      4096
#define ROWS     32768      // B*H*Q rows of attn_weights
#define START    4
#define HEAVY    409        // int(4096*0.1)
#define RSTART   3687       // 4096 - min(409,512)
#define NCAND    3683       // RSTART - START
#define NKEEP    822        // 4 + 409 + 409
#define HEADS    32
#define HDIM     128
#define JCHUNK   461        // ceil(3683/8)

// Scratch (static __device__ — no allocation inside kernel_launch)
__device__ double g_sums[SEQ];
__device__ int    g_rank[SEQ];
__device__ int    g_keep[NKEEP];

// ---------------------------------------------------------------- init
__global__ void k_init() {
    int t = blockIdx.x * blockDim.x + threadIdx.x;
    if (t < SEQ) { g_sums[t] = 0.0; g_rank[t] = 0; }
}

// ------------------------------------------------- column sums (512 MB read)
// blockDim = 1024; thread t owns columns [4t, 4t+4) via float4.
// fp32 chunk accumulation (32 rows) flushed into fp64 to keep the mean
// accurate to ~1e-9 (top-k boundary spacing is ~2e-6).
__global__ void __launch_bounds__(1024, 2) k_colsum(const float* __restrict__ w) {
    int t = threadIdx.x;
    const float4* __restrict__ w4 = (const float4*)w;
    double a0 = 0, a1 = 0, a2 = 0, a3 = 0;
    float  c0 = 0, c1 = 0, c2 = 0, c3 = 0;
    int cnt = 0;
    for (int row = blockIdx.x; row < ROWS; row += gridDim.x) {
        float4 v = w4[(size_t)row * 1024 + t];
        c0 += v.x; c1 += v.y; c2 += v.z; c3 += v.w;
        if (++cnt == 32) {
            a0 += c0; a1 += c1; a2 += c2; a3 += c3;
            c0 = c1 = c2 = c3 = 0.f; cnt = 0;
        }
    }
    a0 += c0; a1 += c1; a2 += c2; a3 += c3;
    int s = 4 * t;
    atomicAdd(&g_sums[s + 0], a0);
    atomicAdd(&g_sums[s + 1], a1);
    atomicAdd(&g_sums[s + 2], a2);
    atomicAdd(&g_sums[s + 3], a3);
}

// ------------------------------------------------- rank via pairwise count
// grid (8, 8): x = candidate chunk (512 each), y = j chunk (461 each).
// All sums are positive doubles -> u64 bit pattern is order-isomorphic.
// Tie-break (equal value, lower index wins) matches jax.lax.top_k.
__global__ void k_rank() {
    __shared__ unsigned long long sj[JCHUNK];
    int j0 = blockIdx.y * JCHUNK;
    for (int k = threadIdx.x; k < JCHUNK; k += blockDim.x) {
        int j = j0 + k;
        sj[k] = (j < NCAND) ? __double_as_longlong(g_sums[START + j]) : 0ULL;
    }
    __syncthreads();
    int i = blockIdx.x * blockDim.x + threadIdx.x;
    if (i >= NCAND) return;
    unsigned long long vi = __double_as_longlong(g_sums[START + i]);
    int jend = min(JCHUNK, NCAND - j0);
    int cnt = 0;
    #pragma unroll 4
    for (int k = 0; k < jend; k++) {
        unsigned long long vj = sj[k];
        if (vj > vi || (vj == vi && (j0 + k) < i)) cnt++;
    }
    if (cnt) atomicAdd(&g_rank[i], cnt);
}

// ------------------------------------------------- build sorted keep list
// Single block, 1024 threads; 4 candidates per thread; block-wide exclusive
// scan over heavy flags gives each heavy index its slot in [START, START+HEAVY).
__global__ void k_build() {
    __shared__ int warpsum[32];
    int t = threadIdx.x;
    int base = 4 * t;
    int f[4], loc = 0;
    #pragma unroll
    for (int k = 0; k < 4; k++) {
        int c = base + k;
        f[k] = (c < NCAND && g_rank[c] < HEAVY) ? 1 : 0;
        loc += f[k];
    }
    int lane = t & 31, w = t >> 5;
    int v = loc;
    #pragma unroll
    for (int o = 1; o < 32; o <<= 1) {
        int n = __shfl_up_sync(0xFFFFFFFFu, v, o);
        if (lane >= o) v += n;
    }
    if (lane == 31) warpsum[w] = v;
    __syncthreads();
    if (w == 0) {
        int s = warpsum[lane];
        #pragma unroll
        for (int o = 1; o < 32; o <<= 1) {
            int n = __shfl_up_sync(0xFFFFFFFFu, s, o);
            if (lane >= o) s += n;
        }
        warpsum[lane] = s;
    }
    __syncthreads();
    int excl = v - loc + (w > 0 ? warpsum[w - 1] : 0);
    int pos = excl;
    #pragma unroll
    for (int k = 0; k < 4; k++) {
        if (f[k]) { g_keep[START + pos] = START + base + k; pos++; }
    }
    if (t < START) g_keep[t] = t;
    for (int r = t; r < SEQ - RSTART; r += blockDim.x)
        g_keep[START + HEAVY + r] = RSTART + r;
}

// ------------------------------------------------- gather rows (float4)
// out layout: [new_keys (32*822*128 f32), new_values (32*822*128 f32)]
__global__ void k_gather(const float4* __restrict__ keys,
                         const float4* __restrict__ vals,
                         float4* __restrict__ out) {
    const int total = 2 * HEADS * NKEEP * (HDIM / 4);  // 1,683,456
    for (int v = blockIdx.x * blockDim.x + threadIdx.x; v < total;
         v += gridDim.x * blockDim.x) {
        int d4  = v & 31;
        int row = v >> 5;                 // 0 .. 2*32*822-1
        int tensor = row / (HEADS * NKEEP);
        int hr  = row - tensor * (HEADS * NKEEP);
        int h   = hr / NKEEP;
        int r   = hr - h * NKEEP;
        int s   = __ldg(&g_keep[r]);
        const float4* __restrict__ src = tensor ? vals : keys;
        out[v] = src[(((size_t)h * SEQ + s) << 5) + d4];
    }
}

extern "C" void kernel_launch(void* const* d_in, const int* in_sizes, int n_in,
                              void* d_out, int out_size) {
    const float* keys = (const float*)d_in[0];   // (1,32,4096,128)
    const float* vals = (const float*)d_in[1];   // (1,32,4096,128)
    const float* attn = (const float*)d_in[2];   // (1,32,1024,4096)
    float* out = (float*)d_out;                  // 2*32*822*128 f32

    k_init<<<4, 1024>>>();
    k_colsum<<<296, 1024>>>(attn);
    {
        dim3 g(8, 8);
        k_rank<<<g, 512>>>();
    }
    k_build<<<1, 1024>>>();
    {
        const int total4 = 2 * HEADS * NKEEP * (HDIM / 4);
        int blocks = (total4 + 255) / 256;
        k_gather<<<blocks, 256>>>((const float4*)keys, (const float4*)vals,
                                  (float4*)out);
    }
}

// round 2
// speedup vs baseline: 1.1067x; 1.1067x over previous
#include <cuda_runtime.h>

// Problem constants (B=1, H=32, Q=1024, S=4096, D=128)
#define SEQ      4096
#define ROWS     32768      // B*H*Q rows of attn_weights
#define START    4
#define HEAVY    409        // int(4096*0.1)
#define RSTART   3687       // 4096 - min(409,512)
#define NCAND    3683       // RSTART - START
#define NKEEP    822        // 4 + 409 + 409
#define HEADS    32
#define HDIM     128
#define JCHUNK   461        // ceil(3683/8)

// Scratch (static __device__ — no allocation inside kernel_launch)
__device__ double g_sums[SEQ];
__device__ int    g_rank[SEQ];
__device__ int    g_keep[NKEEP];

// ---------------------------------------------------------------- init
__global__ void k_init() {
    int t = blockIdx.x * blockDim.x + threadIdx.x;
    if (t < SEQ) { g_sums[t] = 0.0; g_rank[t] = 0; }
}

// ------------------------------------------------- column sums (512 MB read)
// blockDim = 1024; thread t owns columns [4t, 4t+4) via float4.
// Unroll-by-8 rows: 8 independent LDG.128 front-batched per thread (MLP=8)
// so each warp keeps ~4KB in flight; __ldcs since the stream has no reuse.
// fp32 accumulation over 32 rows flushed into fp64 keeps the mean accurate
// to ~1e-9 (top-k boundary spacing is ~2e-6) — matched reference exactly.
__global__ void __launch_bounds__(1024, 1) k_colsum(const float* __restrict__ w) {
    const int t = threadIdx.x;
    const int G = gridDim.x;
    const float4* __restrict__ w4 = (const float4*)w + t;
    double a0 = 0, a1 = 0, a2 = 0, a3 = 0;
    float  c0 = 0, c1 = 0, c2 = 0, c3 = 0;
    int row = blockIdx.x;
    int grp = 0;
    // main: groups of 8 rows, loads front-batched
    for (; row + 7 * G < ROWS; row += 8 * G) {
        float4 v[8];
        #pragma unroll
        for (int k = 0; k < 8; k++)
            v[k] = __ldcs(&w4[(size_t)(row + k * G) * 1024]);
        // pairwise partial sums (better fp32 accuracy + shorter dep chain)
        float s0x = (v[0].x + v[1].x) + (v[2].x + v[3].x);
        float s1x = (v[4].x + v[5].x) + (v[6].x + v[7].x);
        float s0y = (v[0].y + v[1].y) + (v[2].y + v[3].y);
        float s1y = (v[4].y + v[5].y) + (v[6].y + v[7].y);
        float s0z = (v[0].z + v[1].z) + (v[2].z + v[3].z);
        float s1z = (v[4].z + v[5].z) + (v[6].z + v[7].z);
        float s0w = (v[0].w + v[1].w) + (v[2].w + v[3].w);
        float s1w = (v[4].w + v[5].w) + (v[6].w + v[7].w);
        c0 += s0x + s1x;
        c1 += s0y + s1y;
        c2 += s0z + s1z;
        c3 += s0w + s1w;
        if (++grp == 4) {                 // flush every 32 rows (as before)
            a0 += c0; a1 += c1; a2 += c2; a3 += c3;
            c0 = c1 = c2 = c3 = 0.f; grp = 0;
        }
    }
    // remainder rows
    for (; row < ROWS; row += G) {
        float4 v = __ldcs(&w4[(size_t)row * 1024]);
        c0 += v.x; c1 += v.y; c2 += v.z; c3 += v.w;
    }
    a0 += c0; a1 += c1; a2 += c2; a3 += c3;
    int s = 4 * t;
    atomicAdd(&g_sums[s + 0], a0);
    atomicAdd(&g_sums[s + 1], a1);
    atomicAdd(&g_sums[s + 2], a2);
    atomicAdd(&g_sums[s + 3], a3);
}

// ------------------------------------------------- rank via pairwise count
// grid (8, 8): x = candidate chunk (512 each), y = j chunk (461 each).
// All sums are positive doubles -> u64 bit pattern is order-isomorphic.
// Tie-break (equal value, lower index wins) matches jax.lax.top_k.
__global__ void k_rank() {
    __shared__ unsigned long long sj[JCHUNK];
    int j0 = blockIdx.y * JCHUNK;
    for (int k = threadIdx.x; k < JCHUNK; k += blockDim.x) {
        int j = j0 + k;
        sj[k] = (j < NCAND) ? __double_as_longlong(g_sums[START + j]) : 0ULL;
    }
    __syncthreads();
    int i = blockIdx.x * blockDim.x + threadIdx.x;
    if (i >= NCAND) return;
    unsigned long long vi = __double_as_longlong(g_sums[START + i]);
    int jend = min(JCHUNK, NCAND - j0);
    int cnt = 0;
    #pragma unroll 4
    for (int k = 0; k < jend; k++) {
        unsigned long long vj = sj[k];
        if (vj > vi || (vj == vi && (j0 + k) < i)) cnt++;
    }
    if (cnt) atomicAdd(&g_rank[i], cnt);
}

// ------------------------------------------------- build sorted keep list
// Single block, 1024 threads; 4 candidates per thread; block-wide exclusive
// scan over heavy flags gives each heavy index its slot in [START, START+HEAVY).
__global__ void k_build() {
    __shared__ int warpsum[32];
    int t = threadIdx.x;
    int base = 4 * t;
    int f[4], loc = 0;
    #pragma unroll
    for (int k = 0; k < 4; k++) {
        int c = base + k;
        f[k] = (c < NCAND && g_rank[c] < HEAVY) ? 1 : 0;
        loc += f[k];
    }
    int lane = t & 31, w = t >> 5;
    int v = loc;
    #pragma unroll
    for (int o = 1; o < 32; o <<= 1) {
        int n = __shfl_up_sync(0xFFFFFFFFu, v, o);
        if (lane >= o) v += n;
    }
    if (lane == 31) warpsum[w] = v;
    __syncthreads();
    if (w == 0) {
        int s = warpsum[lane];
        #pragma unroll
        for (int o = 1; o < 32; o <<= 1) {
            int n = __shfl_up_sync(0xFFFFFFFFu, s, o);
            if (lane >= o) s += n;
        }
        warpsum[lane] = s;
    }
    __syncthreads();
    int excl = v - loc + (w > 0 ? warpsum[w - 1] : 0);
    int pos = excl;
    #pragma unroll
    for (int k = 0; k < 4; k++) {
        if (f[k]) { g_keep[START + pos] = START + base + k; pos++; }
    }
    if (t < START) g_keep[t] = t;
    for (int r = t; r < SEQ - RSTART; r += blockDim.x)
        g_keep[START + HEAVY + r] = RSTART + r;
}

// ------------------------------------------------- gather rows (float4)
// out layout: [new_keys (32*822*128 f32), new_values (32*822*128 f32)]
__global__ void k_gather(const float4* __restrict__ keys,
                         const float4* __restrict__ vals,
                         float4* __restrict__ out) {
    const int total = 2 * HEADS * NKEEP * (HDIM / 4);  // 1,683,456
    for (int v = blockIdx.x * blockDim.x + threadIdx.x; v < total;
         v += gridDim.x * blockDim.x) {
        int d4  = v & 31;
        int row = v >> 5;                 // 0 .. 2*32*822-1
        int tensor = row / (HEADS * NKEEP);
        int hr  = row - tensor * (HEADS * NKEEP);
        int h   = hr / NKEEP;
        int r   = hr - h * NKEEP;
        int s   = __ldg(&g_keep[r]);
        const float4* __restrict__ src = tensor ? vals : keys;
        out[v] = __ldcs(&src[(((size_t)h * SEQ + s) << 5) + d4]);
    }
}

extern "C" void kernel_launch(void* const* d_in, const int* in_sizes, int n_in,
                              void* d_out, int out_size) {
    const float* keys = (const float*)d_in[0];   // (1,32,4096,128)
    const float* vals = (const float*)d_in[1];   // (1,32,4096,128)
    const float* attn = (const float*)d_in[2];   // (1,32,1024,4096)
    float* out = (float*)d_out;                  // 2*32*822*128 f32

    k_init<<<4, 1024>>>();
    k_colsum<<<296, 1024>>>(attn);
    {
        dim3 g(8, 8);
        k_rank<<<g, 512>>>();
    }
    k_build<<<1, 1024>>>();
    {
        const int total4 = 2 * HEADS * NKEEP * (HDIM / 4);
        int blocks = (total4 + 255) / 256;
        k_gather<<<blocks, 256>>>((const float4*)keys, (const float4*)vals,
                                  (float4*)out);
    }
}

// round 3
// speedup vs baseline: 1.1264x; 1.0178x over previous
#include <cuda_runtime.h>

// Problem constants (B=1, H=32, Q=1024, S=4096, D=128)
#define SEQ      4096
#define ROWS     32768      // B*H*Q rows of attn_weights
#define START    4
#define HEAVY    409        // int(4096*0.1)
#define RSTART   3687       // 4096 - min(409,512)
#define NCAND    3683       // RSTART - START
#define NKEEP    822        // 4 + 409 + 409
#define HEADS    32
#define HDIM     128
#define JCHUNK   461        // ceil(3683/8)
#define NRANKBLK 64         // 8 x-chunks * 8 y-chunks

// Scratch (static __device__, zero-initialized at load; k_gather re-zeroes
// g_sums/g_rank at the end of every call, and the rank kernel's last block
// resets g_done — so every kernel_launch call starts from the same state).
__device__ double g_sums[SEQ];
__device__ int    g_rank[SEQ];
__device__ int    g_keep[NKEEP];
__device__ int    g_done;

// ------------------------------------------------- column sums (512 MB read)
// 148 blocks (exactly one wave), each owning a CONTIGUOUS row range.
// blockDim = 1024; thread t owns columns [4t, 4t+4) via float4.
// 8 independent LDG.128 front-batched per thread (MLP=8); __ldcs (no reuse).
// fp32 accumulation over 32 rows flushed into fp64: mean accurate to ~1e-8
// relative, vs ~1e-5 top-k boundary spacing — index set matches exactly.
__global__ void __launch_bounds__(1024, 1) k_colsum(const float* __restrict__ w) {
    const int t = threadIdx.x;
    const int b = blockIdx.x;
    const int G = gridDim.x;
    const int r0 = (int)((long long)ROWS * b / G);
    const int r1 = (int)((long long)ROWS * (b + 1) / G);
    const float4* __restrict__ w4 = (const float4*)w + t;
    double a0 = 0, a1 = 0, a2 = 0, a3 = 0;
    float  c0 = 0, c1 = 0, c2 = 0, c3 = 0;
    int row = r0;
    int grp = 0;
    for (; row + 8 <= r1; row += 8) {
        float4 v[8];
        #pragma unroll
        for (int k = 0; k < 8; k++)
            v[k] = __ldcs(&w4[(size_t)(row + k) * 1024]);
        float s0x = (v[0].x + v[1].x) + (v[2].x + v[3].x);
        float s1x = (v[4].x + v[5].x) + (v[6].x + v[7].x);
        float s0y = (v[0].y + v[1].y) + (v[2].y + v[3].y);
        float s1y = (v[4].y + v[5].y) + (v[6].y + v[7].y);
        float s0z = (v[0].z + v[1].z) + (v[2].z + v[3].z);
        float s1z = (v[4].z + v[5].z) + (v[6].z + v[7].z);
        float s0w = (v[0].w + v[1].w) + (v[2].w + v[3].w);
        float s1w = (v[4].w + v[5].w) + (v[6].w + v[7].w);
        c0 += s0x + s1x;
        c1 += s0y + s1y;
        c2 += s0z + s1z;
        c3 += s0w + s1w;
        if (++grp == 4) {                 // flush every 32 rows
            a0 += c0; a1 += c1; a2 += c2; a3 += c3;
            c0 = c1 = c2 = c3 = 0.f; grp = 0;
        }
    }
    for (; row < r1; row++) {
        float4 v = __ldcs(&w4[(size_t)row * 1024]);
        c0 += v.x; c1 += v.y; c2 += v.z; c3 += v.w;
    }
    a0 += c0; a1 += c1; a2 += c2; a3 += c3;
    int s = 4 * t;
    atomicAdd(&g_sums[s + 0], a0);
    atomicAdd(&g_sums[s + 1], a1);
    atomicAdd(&g_sums[s + 2], a2);
    atomicAdd(&g_sums[s + 3], a3);
}

// ------------------------------- rank (pairwise count) + fused build
// 64 blocks of 512: block = (x = i-chunk of 512, y = j-chunk of 461).
// All sums are positive doubles -> u64 bit pattern is order-isomorphic.
// Tie-break (equal value, lower index wins) matches jax.lax.top_k.
// Last-arriving block performs the keep-list build (reads g_rank via __ldcg).
__global__ void __launch_bounds__(512) k_rank_build() {
    __shared__ unsigned long long sj[JCHUNK];
    __shared__ int warpsum[16];
    __shared__ int sflag;
    const int t = threadIdx.x;
    const int bx = blockIdx.x & 7;
    const int by = blockIdx.x >> 3;
    const int j0 = by * JCHUNK;
    for (int k = t; k < JCHUNK; k += 512) {
        int j = j0 + k;
        sj[k] = (j < NCAND) ? __double_as_longlong(g_sums[START + j]) : 0ULL;
    }
    __syncthreads();
    {
        int i = bx * 512 + t;
        if (i < NCAND) {
            unsigned long long vi = __double_as_longlong(g_sums[START + i]);
            int jend = min(JCHUNK, NCAND - j0);
            int cnt = 0;
            #pragma unroll 4
            for (int k = 0; k < jend; k++) {
                unsigned long long vj = sj[k];
                if (vj > vi || (vj == vi && (j0 + k) < i)) cnt++;
            }
            if (cnt) atomicAdd(&g_rank[i], cnt);
        }
    }
    // ---- last-block detection ----
    __threadfence();
    __syncthreads();
    if (t == 0) sflag = (atomicAdd(&g_done, 1) == NRANKBLK - 1) ? 1 : 0;
    __syncthreads();
    if (!sflag) return;

    // ---- build sorted keep list (512 threads, 8 candidates each) ----
    int f[8], loc = 0;
    int base = 8 * t;
    #pragma unroll
    for (int k = 0; k < 8; k++) {
        int c = base + k;
        f[k] = (c < NCAND && __ldcg(&g_rank[c]) < HEAVY) ? 1 : 0;
        loc += f[k];
    }
    int lane = t & 31, w = t >> 5;
    int v = loc;
    #pragma unroll
    for (int o = 1; o < 32; o <<= 1) {
        int n = __shfl_up_sync(0xFFFFFFFFu, v, o);
        if (lane >= o) v += n;
    }
    if (lane == 31) warpsum[w] = v;
    __syncthreads();
    if (w == 0 && lane < 16) {
        int s = warpsum[lane];
        #pragma unroll
        for (int o = 1; o < 16; o <<= 1) {
            int n = __shfl_up_sync(0x0000FFFFu, s, o);
            if (lane >= o) s += n;
        }
        warpsum[lane] = s;
    }
    __syncthreads();
    int excl = v - loc + (w > 0 ? warpsum[w - 1] : 0);
    int pos = excl;
    #pragma unroll
    for (int k = 0; k < 8; k++) {
        if (f[k]) { g_keep[START + pos] = START + base + k; pos++; }
    }
    if (t < START) g_keep[t] = t;
    for (int r = t; r < SEQ - RSTART; r += 512)
        g_keep[START + HEAVY + r] = RSTART + r;
    if (t == 0) g_done = 0;   // reset for next call
}

// ------------------------------------------------- gather rows (float4)
// out layout: [new_keys (32*822*128 f32), new_values (32*822*128 f32)]
// Block 0 additionally re-zeroes g_sums/g_rank for the next call (their
// consumers have all completed by the time this kernel runs).
__global__ void k_gather(const float4* __restrict__ keys,
                         const float4* __restrict__ vals,
                         float4* __restrict__ out) {
    if (blockIdx.x == 0) {
        for (int i = threadIdx.x; i < SEQ; i += blockDim.x) {
            g_sums[i] = 0.0;
            g_rank[i] = 0;
        }
    }
    const int total = 2 * HEADS * NKEEP * (HDIM / 4);  // 1,683,456
    for (int v = blockIdx.x * blockDim.x + threadIdx.x; v < total;
         v += gridDim.x * blockDim.x) {
        int d4  = v & 31;
        int row = v >> 5;                 // 0 .. 2*32*822-1
        int tensor = row / (HEADS * NKEEP);
        int hr  = row - tensor * (HEADS * NKEEP);
        int h   = hr / NKEEP;
        int r   = hr - h * NKEEP;
        int s   = __ldg(&g_keep[r]);
        const float4* __restrict__ src = tensor ? vals : keys;
        out[v] = __ldcs(&src[(((size_t)h * SEQ + s) << 5) + d4]);
    }
}

extern "C" void kernel_launch(void* const* d_in, const int* in_sizes, int n_in,
                              void* d_out, int out_size) {
    const float* keys = (const float*)d_in[0];   // (1,32,4096,128)
    const float* vals = (const float*)d_in[1];   // (1,32,4096,128)
    const float* attn = (const float*)d_in[2];   // (1,32,1024,4096)
    float* out = (float*)d_out;                  // 2*32*822*128 f32

    k_colsum<<<148, 1024>>>(attn);
    k_rank_build<<<NRANKBLK, 512>>>();
    {
        const int total4 = 2 * HEADS * NKEEP * (HDIM / 4);
        int blocks = (total4 + 255) / 256;
        k_gather<<<blocks, 256>>>((const float4*)keys, (const float4*)vals,
                                  (float4*)out);
    }
}

// round 4
// speedup vs baseline: 1.1267x; 1.0003x over previous
#include <cuda_runtime.h>

// Problem constants (B=1, H=32, Q=1024, S=4096, D=128)
#define SEQ      4096
#define ROWS     32768      // B*H*Q rows of attn_weights
#define START    4
#define HEAVY    409        // int(4096*0.1)
#define RSTART   3687       // 4096 - min(409,512)
#define NCAND    3683       // RSTART - START
#define NKEEP    822        // 4 + 409 + 409
#define HEADS    32
#define NBLK     148        // one exact wave, all co-resident
#define NTHR     1024
#define ICH      25         // candidates per block in rank phase (148*25>=3683)
#define NFIX     413        // START + recent rows (attention-independent)
#define TOTAL_F  (2*HEADS*NFIX*32)    // fixed-gather float4 count  = 845824
#define TOTAL_H  (2*HEADS*HEAVY*32)   // heavy-gather float4 count  = 837632

// Scratch: all write-before-read within one call (no zero-init needed),
// except barrier counters which are reset in later protected regions.
__device__ double g_partial[NBLK][SEQ];
__device__ double g_sums[SEQ];
__device__ int    g_rank[NCAND];
__device__ int    g_cnt[3];
__device__ int    g_done;

// Software grid barrier: all NBLK blocks are co-resident (grid == one wave).
__device__ __forceinline__ void grid_bar(int idx) {
    __syncthreads();
    if (threadIdx.x == 0) {
        __threadfence();
        atomicAdd(&g_cnt[idx], 1);
        while (*(volatile int*)&g_cnt[idx] < NBLK) { }
        __threadfence();
    }
    __syncthreads();
}

__global__ void __launch_bounds__(NTHR, 1)
k_fused(const float4* __restrict__ keys,
        const float4* __restrict__ vals,
        const float*  __restrict__ attn,
        float4* __restrict__ out) {
    __shared__ unsigned long long sj[NCAND];   // rank phase: all candidate sums
    __shared__ int s_keep[HEAVY];              // build phase: heavy source idxs
    __shared__ int warpsum[32];

    const int t = threadIdx.x;
    const int b = blockIdx.x;

    // ================= Phase A: column partial sums (512 MB stream) ========
    // Contiguous row range per block; thread t owns columns [4t,4t+4).
    // 8 front-batched LDG.128 (MLP=8), __ldcs (no reuse). fp32 over 32 rows
    // flushed into fp64 -> mean accurate to ~1e-8 rel (boundary gap ~1e-5).
    {
        const int r0 = (int)((long long)ROWS * b / NBLK);
        const int r1 = (int)((long long)ROWS * (b + 1) / NBLK);
        const float4* __restrict__ w4 = (const float4*)attn + t;
        double a0 = 0, a1 = 0, a2 = 0, a3 = 0;
        float  c0 = 0, c1 = 0, c2 = 0, c3 = 0;
        int row = r0, grp = 0;
        for (; row + 8 <= r1; row += 8) {
            float4 v[8];
            #pragma unroll
            for (int k = 0; k < 8; k++)
                v[k] = __ldcs(&w4[(size_t)(row + k) * 1024]);
            float s0x = (v[0].x + v[1].x) + (v[2].x + v[3].x);
            float s1x = (v[4].x + v[5].x) + (v[6].x + v[7].x);
            float s0y = (v[0].y + v[1].y) + (v[2].y + v[3].y);
            float s1y = (v[4].y + v[5].y) + (v[6].y + v[7].y);
            float s0z = (v[0].z + v[1].z) + (v[2].z + v[3].z);
            float s1z = (v[4].z + v[5].z) + (v[6].z + v[7].z);
            float s0w = (v[0].w + v[1].w) + (v[2].w + v[3].w);
            float s1w = (v[4].w + v[5].w) + (v[6].w + v[7].w);
            c0 += s0x + s1x;  c1 += s0y + s1y;
            c2 += s0z + s1z;  c3 += s0w + s1w;
            if (++grp == 4) {
                a0 += c0; a1 += c1; a2 += c2; a3 += c3;
                c0 = c1 = c2 = c3 = 0.f; grp = 0;
            }
        }
        for (; row < r1; row++) {
            float4 v = __ldcs(&w4[(size_t)row * 1024]);
            c0 += v.x; c1 += v.y; c2 += v.z; c3 += v.w;
        }
        a0 += c0; a1 += c1; a2 += c2; a3 += c3;
        int s = 4 * t;
        g_partial[b][s + 0] = a0;
        g_partial[b][s + 1] = a1;
        g_partial[b][s + 2] = a2;
        g_partial[b][s + 3] = a3;
    }

    // ---- Phase A': attention-independent gather (sinks + recent window) ---
    // Overlapped into the DRAM-bound phase; no dependency on the sums.
    for (int v = b * NTHR + t; v < TOTAL_F; v += NBLK * NTHR) {
        int d4  = v & 31;
        int row = v >> 5;
        int tensor = row / (HEADS * NFIX);
        int rem = row - tensor * (HEADS * NFIX);
        int h   = rem / NFIX;
        int p   = rem - h * NFIX;                 // 0..412
        int r   = (p < START) ? p : p + HEAVY;    // output row in keep order
        int s   = (p < START) ? p : (RSTART + p - START);
        const float4* __restrict__ src = tensor ? vals : keys;
        out[(((size_t)(tensor * HEADS + h) * NKEEP + r) << 5) + d4] =
            __ldcs(&src[(((size_t)h * SEQ + s) << 5) + d4]);
    }

    grid_bar(0);

    // ================= Phase B1: reduce partials -> column sums ============
    // Block b owns a contiguous column slice (<=28 cols); warp per column,
    // lanes stride the 148 partials, deterministic butterfly reduce.
    {
        const int c0 = (b * SEQ) / NBLK;
        const int c1 = ((b + 1) * SEQ) / NBLK;
        const int w = t >> 5, lane = t & 31;
        int c = c0 + w;
        if (c < c1) {
            double s = 0;
            #pragma unroll
            for (int k = 0; k < 5; k++) {
                int r = lane + 32 * k;
                if (r < NBLK) s += __ldcg(&g_partial[r][c]);
            }
            #pragma unroll
            for (int o = 16; o; o >>= 1)
                s += __shfl_xor_sync(0xFFFFFFFFu, s, o);
            if (lane == 0) g_sums[c] = s;
        }
    }

    grid_bar(1);
    if (b == 0 && t == 0) g_cnt[0] = 0;   // all blocks are past barrier 0

    // ================= Phase B2: rank via pairwise count ===================
    // Positive doubles -> u64 bit order isomorphic. Tie-break (equal value,
    // lower index wins) matches jax.lax.top_k. Block owns 25 candidates,
    // one warp per candidate, no atomics.
    for (int k = t; k < NCAND; k += NTHR)
        sj[k] = __double_as_longlong(__ldcg(&g_sums[START + k]));
    __syncthreads();
    {
        const int w = t >> 5, lane = t & 31;
        if (w < ICH) {
            int i = b * ICH + w;
            if (i < NCAND) {
                unsigned long long vi = sj[i];
                int cnt = 0;
                for (int j = lane; j < NCAND; j += 32) {
                    unsigned long long vj = sj[j];
                    if (vj > vi || (vj == vi && j < i)) cnt++;
                }
                #pragma unroll
                for (int o = 16; o; o >>= 1)
                    cnt += __shfl_down_sync(0xFFFFFFFFu, cnt, o);
                if (lane == 0) g_rank[i] = cnt;
            }
        }
    }

    grid_bar(2);
    if (b == 0 && t == 0) g_cnt[1] = 0;   // all blocks are past barrier 1

    // ================= Phase C: build heavy keep list (redundant/block) ====
    // Each block computes the same scan into its own smem -> no 4th barrier.
    {
        int f[4], loc = 0;
        int base = 4 * t;
        #pragma unroll
        for (int k = 0; k < 4; k++) {
            int c = base + k;
            f[k] = (c < NCAND && __ldcg(&g_rank[c]) < HEAVY) ? 1 : 0;
            loc += f[k];
        }
        int lane = t & 31, w = t >> 5;
        int v = loc;
        #pragma unroll
        for (int o = 1; o < 32; o <<= 1) {
            int n = __shfl_up_sync(0xFFFFFFFFu, v, o);
            if (lane >= o) v += n;
        }
        if (lane == 31) warpsum[w] = v;
        __syncthreads();
        if (w == 0) {
            int s = warpsum[lane];
            #pragma unroll
            for (int o = 1; o < 32; o <<= 1) {
                int n = __shfl_up_sync(0xFFFFFFFFu, s, o);
                if (lane >= o) s += n;
            }
            warpsum[lane] = s;
        }
        __syncthreads();
        int pos = v - loc + (w > 0 ? warpsum[w - 1] : 0);
        #pragma unroll
        for (int k = 0; k < 4; k++) {
            if (f[k]) { s_keep[pos] = START + base + k; pos++; }
        }
    }
    __syncthreads();

    // ================= Phase D: heavy-row gather ===========================
    for (int v = b * NTHR + t; v < TOTAL_H; v += NBLK * NTHR) {
        int d4  = v & 31;
        int row = v >> 5;
        int tensor = row / (HEADS * HEAVY);
        int rem = row - tensor * (HEADS * HEAVY);
        int h   = rem / HEAVY;
        int q   = rem - h * HEAVY;                // heavy slot 0..408
        int s   = s_keep[q];
        const float4* __restrict__ src = tensor ? vals : keys;
        out[(((size_t)(tensor * HEADS + h) * NKEEP + (START + q)) << 5) + d4] =
            __ldcs(&src[(((size_t)h * SEQ + s) << 5) + d4]);
    }

    // ---- epilogue: last block resets remaining barrier state --------------
    __syncthreads();
    if (t == 0) {
        if (atomicAdd(&g_done, 1) == NBLK - 1) {
            g_cnt[2] = 0;
            g_done = 0;
        }
    }
}

extern "C" void kernel_launch(void* const* d_in, const int* in_sizes, int n_in,
                              void* d_out, int out_size) {
    const float* keys = (const float*)d_in[0];   // (1,32,4096,128)
    const float* vals = (const float*)d_in[1];   // (1,32,4096,128)
    const float* attn = (const float*)d_in[2];   // (1,32,1024,4096)
    float* out = (float*)d_out;                  // 2*32*822*128 f32

    k_fused<<<NBLK, NTHR>>>((const float4*)keys, (const float4*)vals,
                            attn, (float4*)out);
}